// round 14
// baseline (speedup 1.0000x reference)
#include <cuda_runtime.h>
#include <cuda_fp16.h>
#include <cuda_fp8.h>
#include <cstdint>

#define BHALF 4096
#define NROW  8192
#define DIM   256
#define INV_T (1.0f/0.07f)
#define LOG2E 1.4426950408889634f

#define TILE_M 128
#define ST16 272                 // bytes per row, fp16 half-tile (256 + 16 pad)
#define ST8  144                 // bytes per row, fp8 half-tile (128 + 16 pad)
#define A16_BYTES (TILE_M * ST16)        // 34816
#define A8_BYTES  (TILE_M * ST8)         // 18432
#define OFF_A16 0
#define OFF_A8  (OFF_A16 + A16_BYTES)
#define OFF_B16_0 (OFF_A8 + A8_BYTES)
#define OFF_B8_0  (OFF_B16_0 + A16_BYTES)
#define OFF_B16_1 (OFF_B8_0 + A8_BYTES)
#define OFF_B8_1  (OFF_B16_1 + A16_BYTES)
#define SMEM_BYTES (OFF_B8_1 + A8_BYTES)    // 159744

#define NTILE 64
#define NPAIR 2080
#define NTHREADS 512             // 16 warps, 4x4 warp grid, 32x32 per warp

__device__ __half g_zn16[NROW * 128];        // dims 0..127, fp16 (2 MB)
__device__ unsigned char g_zn8[NROW * 128];  // dims 128..255, e4m3 (1 MB)
__device__ float g_sumexp[NROW];
__device__ float g_pos[NROW];
__device__ volatile unsigned g_gen;
__device__ unsigned g_count;
__device__ unsigned g_done;

// ---------------------------------------------------------------------------
__device__ __forceinline__ void grid_barrier(unsigned nblk) {
    __threadfence();
    __syncthreads();
    if (threadIdx.x == 0) {
        unsigned gen = g_gen;
        if (atomicAdd(&g_count, 1) == nblk - 1) {
            g_count = 0;
            __threadfence();
            g_gen = gen + 1;
        } else {
            while (g_gen == gen) {}
            __threadfence();
        }
    }
    __syncthreads();
}

__device__ __forceinline__ float fast_exp2(float y) {
    float t  = y + 12582912.0f;
    int   i  = __float_as_int(t);
    float nf = t - 12582912.0f;
    float f  = y - nf;
    float p  = fmaf(1.3333558e-3f, f, 9.6181291e-3f);
    p = fmaf(p, f, 5.5504109e-2f);
    p = fmaf(p, f, 2.4022651e-1f);
    p = fmaf(p, f, 6.9314718e-1f);
    p = fmaf(p, f, 1.0f);
    return p * __int_as_float((i << 23) + 0x3F800000);
}

// fp16 inputs, fp32 accumulate
__device__ __forceinline__ void mma_f16f32(float c[4],
                                           unsigned a0, unsigned a1, unsigned a2, unsigned a3,
                                           unsigned b0, unsigned b1) {
    asm volatile(
        "mma.sync.aligned.m16n8k16.row.col.f32.f16.f16.f32 "
        "{%0,%1,%2,%3}, {%4,%5,%6,%7}, {%8,%9}, {%0,%1,%2,%3};\n"
        : "+f"(c[0]), "+f"(c[1]), "+f"(c[2]), "+f"(c[3])
        : "r"(a0), "r"(a1), "r"(a2), "r"(a3), "r"(b0), "r"(b1));
}

// fp8 e4m3 inputs, fp32 accumulate
__device__ __forceinline__ void mma_fp8(float c[4],
                                        unsigned a0, unsigned a1, unsigned a2, unsigned a3,
                                        unsigned b0, unsigned b1) {
    asm volatile(
        "mma.sync.aligned.m16n8k32.row.col.f32.e4m3.e4m3.f32 "
        "{%0,%1,%2,%3}, {%4,%5,%6,%7}, {%8,%9}, {%0,%1,%2,%3};\n"
        : "+f"(c[0]), "+f"(c[1]), "+f"(c[2]), "+f"(c[3])
        : "r"(a0), "r"(a1), "r"(a2), "r"(a3), "r"(b0), "r"(b1));
}

__device__ __forceinline__ void ldsm_x4(unsigned* r, uint32_t addr) {
    asm volatile("ldmatrix.sync.aligned.m8n8.x4.shared.b16 {%0,%1,%2,%3}, [%4];"
                 : "=r"(r[0]), "=r"(r[1]), "=r"(r[2]), "=r"(r[3]) : "r"(addr));
}

__device__ __forceinline__ void cp_async16(void* smem_dst, const void* gsrc) {
    unsigned s = (unsigned)__cvta_generic_to_shared(smem_dst);
    asm volatile("cp.async.cg.shared.global [%0], [%1], 16;\n" :: "r"(s), "l"(gsrc));
}
__device__ __forceinline__ void cp_commit() {
    asm volatile("cp.async.commit_group;\n" ::: "memory");
}
__device__ __forceinline__ void cp_wait1() {
    asm volatile("cp.async.wait_group 1;\n" ::: "memory");
}
__device__ __forceinline__ void cp_wait0() {
    asm volatile("cp.async.wait_group 0;\n" ::: "memory");
}

// fp16 half-tile: 128 rows x 256 B  (2048 chunks)
__device__ __forceinline__ void load_tile16_cp(char* dst, const __half* src, int tid) {
    #pragma unroll
    for (int it = 0; it < 4; it++) {
        int idx = tid + it * NTHREADS;
        int r = idx >> 4, c = idx & 15;
        cp_async16(dst + r * ST16 + c * 16, (const char*)src + r * 256 + c * 16);
    }
}
// fp8 half-tile: 128 rows x 128 B  (1024 chunks)
__device__ __forceinline__ void load_tile8_cp(char* dst, const unsigned char* src, int tid) {
    #pragma unroll
    for (int it = 0; it < 2; it++) {
        int idx = tid + it * NTHREADS;
        int r = idx >> 3, c = idx & 7;
        cp_async16(dst + r * ST8 + c * 16, src + r * 128 + c * 16);
    }
}
__device__ __forceinline__ void load_tile16_sync(char* dst, const __half* src, int tid) {
    const uint4* g = (const uint4*)src;
    #pragma unroll
    for (int it = 0; it < 4; it++) {
        int idx = tid + it * NTHREADS;
        int r = idx >> 4, c = idx & 15;
        *(uint4*)(dst + r * ST16 + c * 16) = g[r * 16 + c];
    }
}
__device__ __forceinline__ void load_tile8_sync(char* dst, const unsigned char* src, int tid) {
    const uint4* g = (const uint4*)src;
    #pragma unroll
    for (int it = 0; it < 2; it++) {
        int idx = tid + it * NTHREADS;
        int r = idx >> 3, c = idx & 7;
        *(uint4*)(dst + r * ST8 + c * 16) = g[r * 8 + c];
    }
}

__device__ __forceinline__ void decode_tile(int q, int& i, int& j) {
    i = 0;
    int rem = q;
    while (rem >= NTILE - i) { rem -= NTILE - i; i++; }
    j = i + rem;
}

__device__ __forceinline__ void flush_rsum(float (&rsum)[2][2], int iT,
                                           int wm, int g, int tig) {
    #pragma unroll
    for (int mt = 0; mt < 2; mt++)
        #pragma unroll
        for (int h = 0; h < 2; h++) {
            float v = rsum[mt][h];
            v += __shfl_xor_sync(0xffffffffu, v, 1);
            v += __shfl_xor_sync(0xffffffffu, v, 2);
            if (tig == 0)
                atomicAdd(&g_sumexp[iT * TILE_M + wm * 32 + mt * 16 + g + h * 8], v);
            rsum[mt][h] = 0.0f;
        }
}

__device__ __forceinline__ void flush_csum(float (&csum)[4][2], int jP,
                                           int wn, int g, int tig) {
    #pragma unroll
    for (int nt = 0; nt < 4; nt++)
        #pragma unroll
        for (int p = 0; p < 2; p++) {
            float v = csum[nt][p];
            v += __shfl_xor_sync(0xffffffffu, v, 4);
            v += __shfl_xor_sync(0xffffffffu, v, 8);
            v += __shfl_xor_sync(0xffffffffu, v, 16);
            if (g == 0)
                atomicAdd(&g_sumexp[jP * TILE_M + wn * 32 + nt * 8 + tig * 2 + p], v);
        }
}

// ---------------------------------------------------------------------------
// one-warp row normalize: dims 0..127 -> fp16, dims 128..255 -> e4m3
// ---------------------------------------------------------------------------
__device__ __forceinline__ void norm_row(int row, const float* __restrict__ z_i,
                                         const float* __restrict__ z_j, int lane) {
    const float* src = (row < BHALF) ? (z_i + (size_t)row * DIM)
                                     : (z_j + (size_t)(row - BHALF) * DIM);
    float4 v0 = ((const float4*)src)[lane * 2];
    float4 v1 = ((const float4*)src)[lane * 2 + 1];
    float ss = v0.x*v0.x + v0.y*v0.y + v0.z*v0.z + v0.w*v0.w
             + v1.x*v1.x + v1.y*v1.y + v1.z*v1.z + v1.w*v1.w;
    #pragma unroll
    for (int o = 16; o; o >>= 1) ss += __shfl_xor_sync(0xffffffffu, ss, o);
    float inv = 1.0f / fmaxf(sqrtf(ss), 1e-8f);

    if (lane < 16) {            // dims lane*8 .. lane*8+7 -> fp16
        __half2 h0 = __floats2half2_rn(v0.x*inv, v0.y*inv);
        __half2 h1 = __floats2half2_rn(v0.z*inv, v0.w*inv);
        __half2 h2 = __floats2half2_rn(v1.x*inv, v1.y*inv);
        __half2 h3 = __floats2half2_rn(v1.z*inv, v1.w*inv);
        uint4 u;
        u.x = *(unsigned*)&h0; u.y = *(unsigned*)&h1;
        u.z = *(unsigned*)&h2; u.w = *(unsigned*)&h3;
        *(uint4*)(g_zn16 + (size_t)row * 128 + lane * 8) = u;
    } else {                    // dims 128 + (lane-16)*8 .. -> e4m3
        unsigned p0 = __nv_cvt_float2_to_fp8x2(make_float2(v0.x*inv, v0.y*inv),
                                               __NV_SATFINITE, __NV_E4M3);
        unsigned p1 = __nv_cvt_float2_to_fp8x2(make_float2(v0.z*inv, v0.w*inv),
                                               __NV_SATFINITE, __NV_E4M3);
        unsigned p2 = __nv_cvt_float2_to_fp8x2(make_float2(v1.x*inv, v1.y*inv),
                                               __NV_SATFINITE, __NV_E4M3);
        unsigned p3 = __nv_cvt_float2_to_fp8x2(make_float2(v1.z*inv, v1.w*inv),
                                               __NV_SATFINITE, __NV_E4M3);
        uint2 u;
        u.x = (p0 & 0xffffu) | (p1 << 16);
        u.y = (p2 & 0xffffu) | (p3 << 16);
        *(uint2*)(g_zn8 + (size_t)row * 128 + (lane - 16) * 8) = u;
    }
    if (lane == 0) { g_sumexp[row] = 0.0f; g_pos[row] = 0.0f; }
}

// ---------------------------------------------------------------------------
// fused persistent kernel: normalize -> barrier -> mixed fp16/fp8 K-split
// symmetric GEMM with fused softmax-sum epilogue -> loss tail
// ---------------------------------------------------------------------------
__global__ void __launch_bounds__(NTHREADS) ntxent_fused_kernel(
    const float* __restrict__ z_i, const float* __restrict__ z_j,
    float* __restrict__ out)
{
    extern __shared__ char smem[];

    const int tid  = threadIdx.x;
    const int warp = tid >> 5, lane = tid & 31;
    const int g    = lane >> 2, tig = lane & 3;
    const int wm   = warp >> 2, wn = warp & 3;   // 4x4 grid -> 32x32 per warp
    const unsigned nblk = gridDim.x;

    // ---- phase 1: normalize ----
    {
        int stride = nblk * 16;
        for (int r0 = blockIdx.x * 16 + warp; r0 < NROW; r0 += 2 * stride) {
            int r1 = r0 + stride;
            norm_row(r0, z_i, z_j, lane);
            if (r1 < NROW) norm_row(r1, z_i, z_j, lane);
        }
    }

    grid_barrier(nblk);

    // ---- phase 2: GEMM ----
    int bid = blockIdx.x;
    int q0  = (int)(((long long)bid * NPAIR) / nblk);
    int q1  = (int)(((long long)(bid + 1) * NPAIR) / nblk);

    if (q0 < q1) {
        int iCur, jCur;
        decode_tile(q0, iCur, jCur);

        load_tile16_sync(smem + OFF_A16, g_zn16 + (size_t)iCur * TILE_M * 128, tid);
        load_tile8_sync (smem + OFF_A8,  g_zn8  + (size_t)iCur * TILE_M * 128, tid);
        int iLoaded = iCur;
        load_tile16_cp(smem + OFF_B16_0, g_zn16 + (size_t)jCur * TILE_M * 128, tid);
        load_tile8_cp (smem + OFF_B8_0,  g_zn8  + (size_t)jCur * TILE_M * 128, tid);
        cp_commit();

        const uint32_t sbase = (uint32_t)__cvta_generic_to_shared(smem);
        // fp16 LDSM per-lane offsets (row = lane&15, k-col = (lane>>4)*8 halves)
        const uint32_t a16Off = (uint32_t)((wm * 32 + (lane & 15)) * ST16 + (lane >> 4) * 16);
        const uint32_t b16Off = (uint32_t)((wn * 32 + (lane & 15)) * ST16 + (lane >> 4) * 16);
        const uint32_t STEP16R = 16u * ST16;   // +16 rows

        float rsum[2][2];
        rsum[0][0] = rsum[0][1] = rsum[1][0] = rsum[1][1] = 0.f;

        for (int q = q0; q < q1; q++) {
            int buf = (q - q0) & 1;
            int iN = iCur, jN = jCur + 1;
            if (jN == NTILE) { iN++; jN = iN; }

            __syncthreads();

            if (q + 1 < q1) {
                load_tile16_cp(smem + (buf ? OFF_B16_0 : OFF_B16_1),
                               g_zn16 + (size_t)jN * TILE_M * 128, tid);
                load_tile8_cp (smem + (buf ? OFF_B8_0 : OFF_B8_1),
                               g_zn8  + (size_t)jN * TILE_M * 128, tid);
            }
            cp_commit();

            if (iCur != iLoaded) {
                flush_rsum(rsum, iLoaded, wm, g, tig);
                load_tile16_sync(smem + OFF_A16, g_zn16 + (size_t)iCur * TILE_M * 128, tid);
                load_tile8_sync (smem + OFF_A8,  g_zn8  + (size_t)iCur * TILE_M * 128, tid);
                iLoaded = iCur;
            }

            cp_wait1();
            __syncthreads();

            const uint32_t aA0 = sbase + OFF_A16 + a16Off;
            const uint32_t aA1 = aA0 + STEP16R;
            const uint32_t bB0 = sbase + (buf ? OFF_B16_1 : OFF_B16_0) + b16Off;
            const uint32_t bB1 = bB0 + STEP16R;
            const char* A8 = smem + OFF_A8;
            const char* B8 = smem + (buf ? OFF_B8_1 : OFF_B8_0);

            float acc[2][4][4];
            #pragma unroll
            for (int mt = 0; mt < 2; mt++)
                #pragma unroll
                for (int nt = 0; nt < 4; nt++)
                    #pragma unroll
                    for (int ci = 0; ci < 4; ci++) acc[mt][nt][ci] = 0.f;

            // interleaved mixed-precision mainloop: 8 fp16 kk + 4 fp8 kk
            #pragma unroll
            for (int kk = 0; kk < 8; kk++) {
                // --- fp16 kk (k = kk*16 .. +15 of dims 0..127) ---
                {
                    const uint32_t kb = (uint32_t)kk * 32u;   // 16 halves
                    unsigned af0[4], af1[4], bf0[4], bf1[4];
                    ldsm_x4(af0, aA0 + kb);
                    ldsm_x4(af1, aA1 + kb);
                    ldsm_x4(bf0, bB0 + kb);
                    ldsm_x4(bf1, bB1 + kb);
                    mma_f16f32(acc[0][0], af0[0], af0[1], af0[2], af0[3], bf0[0], bf0[2]);
                    mma_f16f32(acc[0][1], af0[0], af0[1], af0[2], af0[3], bf0[1], bf0[3]);
                    mma_f16f32(acc[0][2], af0[0], af0[1], af0[2], af0[3], bf1[0], bf1[2]);
                    mma_f16f32(acc[0][3], af0[0], af0[1], af0[2], af0[3], bf1[1], bf1[3]);
                    mma_f16f32(acc[1][0], af1[0], af1[1], af1[2], af1[3], bf0[0], bf0[2]);
                    mma_f16f32(acc[1][1], af1[0], af1[1], af1[2], af1[3], bf0[1], bf0[3]);
                    mma_f16f32(acc[1][2], af1[0], af1[1], af1[2], af1[3], bf1[0], bf1[2]);
                    mma_f16f32(acc[1][3], af1[0], af1[1], af1[2], af1[3], bf1[1], bf1[3]);
                }
                // --- fp8 kk (k = kk*32 .. +31 of dims 128..255), first 4 steps ---
                if (kk < 4) {
                    const int k0 = kk * 32 + tig * 4;
                    unsigned a[2][4], b[4][2];
                    #pragma unroll
                    for (int mt = 0; mt < 2; mt++) {
                        const char* ap = A8 + (wm * 32 + mt * 16 + g) * ST8 + k0;
                        a[mt][0] = *(const unsigned*)(ap);
                        a[mt][1] = *(const unsigned*)(ap + 8 * ST8);
                        a[mt][2] = *(const unsigned*)(ap + 16);
                        a[mt][3] = *(const unsigned*)(ap + 8 * ST8 + 16);
                    }
                    #pragma unroll
                    for (int nt = 0; nt < 4; nt++) {
                        const char* bp = B8 + (wn * 32 + nt * 8 + g) * ST8 + k0;
                        b[nt][0] = *(const unsigned*)(bp);
                        b[nt][1] = *(const unsigned*)(bp + 16);
                    }
                    #pragma unroll
                    for (int mt = 0; mt < 2; mt++)
                        #pragma unroll
                        for (int nt = 0; nt < 4; nt++)
                            mma_fp8(acc[mt][nt], a[mt][0], a[mt][1], a[mt][2], a[mt][3],
                                    b[nt][0], b[nt][1]);
                }
            }

            // ---- fused epilogue ----
            const bool diag = (jCur == iCur);
            const bool pos  = (jCur == iCur + 32);
            float csum[4][2];
            #pragma unroll
            for (int nt = 0; nt < 4; nt++) { csum[nt][0] = 0.f; csum[nt][1] = 0.f; }

            #pragma unroll
            for (int mt = 0; mt < 2; mt++)
                #pragma unroll
                for (int nt = 0; nt < 4; nt++)
                    #pragma unroll
                    for (int ci = 0; ci < 4; ci++) {
                        float v = acc[mt][nt][ci];
                        float e = fast_exp2(v * (INV_T * LOG2E));
                        if (diag | pos) {
                            int row = iCur * TILE_M + wm * 32 + mt * 16 + g + (ci >> 1) * 8;
                            int col = jCur * TILE_M + wn * 32 + nt * 8 + tig * 2 + (ci & 1);
                            if (pos & (col == row + BHALF)) {
                                float pv = v * INV_T;
                                g_pos[row] = pv;
                                g_pos[col] = pv;
                            }
                            if (diag & (col == row)) e = 0.0f;
                        }
                        rsum[mt][ci >> 1] += e;
                        csum[nt][ci & 1]  += e;
                    }

            if (!diag) flush_csum(csum, jCur, wn, g, tig);

            iCur = iN; jCur = jN;
        }

        flush_rsum(rsum, iLoaded, wm, g, tig);
        cp_wait0();
    }

    // ---- phase 3: last block computes the loss ----
    __threadfence();
    __syncthreads();
    __shared__ unsigned amLast;
    if (tid == 0)
        amLast = (atomicAdd(&g_done, 1) == nblk - 1) ? 1u : 0u;
    __syncthreads();

    if (amLast) {
        __threadfence();
        float s = 0.0f;
        for (int k = tid; k < NROW; k += NTHREADS)
            s += logf(__ldcg(&g_sumexp[k])) - __ldcg(&g_pos[k]);
        #pragma unroll
        for (int o = 16; o; o >>= 1) s += __shfl_xor_sync(0xffffffffu, s, o);
        __shared__ float sw[16];
        if (lane == 0) sw[warp] = s;
        __syncthreads();
        if (tid == 0) {
            float v = 0.0f;
            #pragma unroll
            for (int w = 0; w < 16; w++) v += sw[w];
            out[0] = v / (float)NROW;
            g_done = 0;
        }
    }
}

extern "C" void kernel_launch(void* const* d_in, const int* in_sizes, int n_in,
                              void* d_out, int out_size) {
    const float* z_i = (const float*)d_in[0];
    const float* z_j = (const float*)d_in[1];
    float* out = (float*)d_out;

    int dev = 0, nsm = 148;
    cudaGetDevice(&dev);
    cudaDeviceGetAttribute(&nsm, cudaDevAttrMultiProcessorCount, dev);
    if (nsm < 1) nsm = 148;
    if (nsm > 512) nsm = 512;

    cudaFuncSetAttribute(ntxent_fused_kernel,
                         cudaFuncAttributeMaxDynamicSharedMemorySize, SMEM_BYTES);

    ntxent_fused_kernel<<<nsm, NTHREADS, SMEM_BYTES>>>(z_i, z_j, out);
}